// round 1
// baseline (speedup 1.0000x reference)
#include <cuda_runtime.h>
#include <cstddef>

#define NP 200000
#define NA 100000
#define NI 8000
#define NF 30000
#define DIM 256
#define OUTD 349
#define E_CITES 500000
#define E_WRITES 400000
#define E_AFF 100000
#define E_TOPIC 300000

#define SZP ((size_t)NP * DIM)

// ---------------- scratch (device globals: no allocation allowed) ----------------
__device__ float g_agg[3 * NP * DIM];      // 3 aggregation slots (max dst = NP)
__device__ float g_p1[NP * DIM];
__device__ float g_a1[NA * DIM];
__device__ float g_f1[NF * DIM];
__device__ float g_p2[NP * DIM];
__device__ float g_inv[6 * NP];            // per-relation 1/max(cnt,1)
__device__ float g_wrp1[DIM * DIM];        // Wr[0,0]+Wr[0,1]+Wr[0,6]
__device__ float g_wra1[DIM * DIM];        // Wr[0,2]+Wr[0,4]
__device__ float g_wrp2[DIM * DIM];        // Wr[1,0]+Wr[1,1]+Wr[1,6]
__device__ float g_woutp[DIM * 384];       // W_out zero-padded to N=384

// ---------------- small kernels ----------------
__global__ void k_count(const int* __restrict__ dst, float* cnt, int E) {
    int i = blockIdx.x * blockDim.x + threadIdx.x;
    if (i < E) atomicAdd(&cnt[dst[i]], 1.0f);
}

__global__ void k_inv(float* cnt, int n) {
    int i = blockIdx.x * blockDim.x + threadIdx.x;
    if (i < n) cnt[i] = 1.0f / fmaxf(cnt[i], 1.0f);
}

__global__ void k_addmats(const float* __restrict__ a, const float* __restrict__ b,
                          const float* __restrict__ c, float* __restrict__ out) {
    int i = blockIdx.x * blockDim.x + threadIdx.x;  // 65536 total
    float v = a[i] + b[i];
    if (c) v += c[i];
    out[i] = v;
}

__global__ void k_pad_wout(const float* __restrict__ W, float* __restrict__ Wp) {
    int i = blockIdx.x * blockDim.x + threadIdx.x;  // 256*384 total
    int r = i / 384, c = i % 384;
    Wp[i] = (c < OUTD) ? W[r * OUTD + c] : 0.0f;
}

// One warp per edge; 2x float4 per lane; 128-bit vector reduction to L2.
__global__ void k_scatter(const float* __restrict__ X, const int* __restrict__ src,
                          const int* __restrict__ dst, float* __restrict__ agg, int E) {
    int gt = blockIdx.x * blockDim.x + threadIdx.x;
    int e = gt >> 5;
    int lane = gt & 31;
    if (e >= E) return;
    int s = __ldg(&src[e]);
    int d = __ldg(&dst[e]);
    const float4* xs = reinterpret_cast<const float4*>(X + (size_t)s * DIM);
    float* ag = agg + (size_t)d * DIM;
#pragma unroll
    for (int j = 0; j < 2; j++) {
        int f4 = lane + j * 32;
        float4 v = __ldg(&xs[f4]);
        asm volatile("red.global.add.v4.f32 [%0], {%1,%2,%3,%4};"
                     :: "l"(ag + f4 * 4), "f"(v.x), "f"(v.y), "f"(v.z), "f"(v.w)
                     : "memory");
    }
}

// ---------------- fused multi-segment SGEMM ----------------
// C[M,Nst] = act( sum_s scale_rows(A_s) @ W_s  + sum_s bias_s )
// A_s: [M,256] row-major, optionally row-scaled by inv_s (mean aggregation).
// W_s: [256, Nld] row-major. Nld is padded load width; Nst is store width / ldc.
struct Seg {
    const float* A;
    const float* inv;
    const float* W;
    const float* bias;
};

template <bool RELU, bool GUARDN>
__global__ __launch_bounds__(256)
void k_gemm(Seg s0, Seg s1, Seg s2, Seg s3, int nseg,
            int M, int Nld, int Nst, float* __restrict__ C) {
    __shared__ float As[16][132];   // transposed A tile, padded (bank spread)
    __shared__ float Bs[16][128];

    Seg segs[4] = {s0, s1, s2, s3};
    const int tid = threadIdx.x;
    const int m0 = blockIdx.y * 128;
    const int n0 = blockIdx.x * 128;
    const int ty = tid >> 4, tx = tid & 15;

    float acc[8][8];
#pragma unroll
    for (int i = 0; i < 8; i++)
#pragma unroll
        for (int j = 0; j < 8; j++) acc[i][j] = 0.0f;

    const int arow = tid >> 2;          // 0..63 (two passes: +0, +64)
    const int acol = (tid & 3) * 4;     // 0,4,8,12
    const int brow = tid >> 5;          // 0..7 (two passes: +0, +8)
    const int bcol = (tid & 31) * 4;    // 0..124

    for (int s = 0; s < nseg; s++) {
        const float* A = segs[s].A;
        const float* inv = segs[s].inv;
        const float* W = segs[s].W;
        for (int kt = 0; kt < 256; kt += 16) {
            // A tile (128 x 16), stored transposed
#pragma unroll
            for (int h = 0; h < 2; h++) {
                int mr = arow + h * 64;
                int gm = m0 + mr;
                float4 v = make_float4(0.f, 0.f, 0.f, 0.f);
                if (gm < M) {
                    v = __ldg(reinterpret_cast<const float4*>(A + (size_t)gm * 256 + kt + acol));
                    if (inv) {
                        float iv = __ldg(&inv[gm]);
                        v.x *= iv; v.y *= iv; v.z *= iv; v.w *= iv;
                    }
                }
                As[acol + 0][mr] = v.x;
                As[acol + 1][mr] = v.y;
                As[acol + 2][mr] = v.z;
                As[acol + 3][mr] = v.w;
            }
            // B tile (16 x 128)
#pragma unroll
            for (int h = 0; h < 2; h++) {
                int kr = brow + h * 8;
                float4 v = __ldg(reinterpret_cast<const float4*>(
                    W + (size_t)(kt + kr) * Nld + n0 + bcol));
                *reinterpret_cast<float4*>(&Bs[kr][bcol]) = v;
            }
            __syncthreads();
#pragma unroll
            for (int kk = 0; kk < 16; kk++) {
                float af[8], bf[8];
#pragma unroll
                for (int i = 0; i < 8; i++) af[i] = As[kk][ty * 8 + i];
#pragma unroll
                for (int j = 0; j < 8; j++) bf[j] = Bs[kk][tx * 8 + j];
#pragma unroll
                for (int i = 0; i < 8; i++)
#pragma unroll
                    for (int j = 0; j < 8; j++) acc[i][j] += af[i] * bf[j];
            }
            __syncthreads();
        }
    }

    // epilogue: sum of biases, optional relu, single store
    float bvec[8];
#pragma unroll
    for (int j = 0; j < 8; j++) {
        int n = n0 + tx * 8 + j;
        float b = 0.0f;
        if (!GUARDN || n < Nst) {
            for (int s = 0; s < nseg; s++)
                if (segs[s].bias) b += __ldg(&segs[s].bias[n]);
        }
        bvec[j] = b;
    }
#pragma unroll
    for (int i = 0; i < 8; i++) {
        int m = m0 + ty * 8 + i;
        if (m >= M) continue;
#pragma unroll
        for (int j = 0; j < 8; j++) {
            int n = n0 + tx * 8 + j;
            if (GUARDN && n >= Nst) continue;
            float v = acc[i][j] + bvec[j];
            if (RELU) v = fmaxf(v, 0.0f);
            C[(size_t)m * Nst + n] = v;
        }
    }
}

// ---------------- orchestration ----------------
static inline int cdiv(int a, int b) { return (a + b - 1) / b; }

extern "C" void kernel_launch(void* const* d_in, const int* in_sizes, int n_in,
                              void* d_out, int out_size) {
    const float* x_p = (const float*)d_in[0];
    const float* x_a = (const float*)d_in[1];
    const float* x_i = (const float*)d_in[2];
    const float* x_f = (const float*)d_in[3];
    const int* cites_src = (const int*)d_in[4];
    const int* cites_dst = (const int*)d_in[5];
    const int* writes_src = (const int*)d_in[6];
    const int* writes_dst = (const int*)d_in[7];
    const int* rev_writes_src = (const int*)d_in[8];
    const int* rev_writes_dst = (const int*)d_in[9];
    // d_in[10], d_in[11]: aff_src/aff_dst (relation unused: layer-1 new_i is dead)
    const int* rev_aff_src = (const int*)d_in[12];
    const int* rev_aff_dst = (const int*)d_in[13];
    const int* topic_src = (const int*)d_in[14];
    const int* topic_dst = (const int*)d_in[15];
    const int* rev_topic_src = (const int*)d_in[16];
    const int* rev_topic_dst = (const int*)d_in[17];
    const float* Wl = (const float*)d_in[18];
    const float* bl = (const float*)d_in[19];
    const float* Wr = (const float*)d_in[20];
    const float* W_out = (const float*)d_in[21];
    const float* b_out = (const float*)d_in[22];

    float *agg, *p1, *a1, *f1, *p2, *invb, *wrp1, *wra1, *wrp2, *woutp;
    cudaGetSymbolAddress((void**)&agg, g_agg);
    cudaGetSymbolAddress((void**)&p1, g_p1);
    cudaGetSymbolAddress((void**)&a1, g_a1);
    cudaGetSymbolAddress((void**)&f1, g_f1);
    cudaGetSymbolAddress((void**)&p2, g_p2);
    cudaGetSymbolAddress((void**)&invb, g_inv);
    cudaGetSymbolAddress((void**)&wrp1, g_wrp1);
    cudaGetSymbolAddress((void**)&wra1, g_wra1);
    cudaGetSymbolAddress((void**)&wrp2, g_wrp2);
    cudaGetSymbolAddress((void**)&woutp, g_woutp);

    auto WLp = [&](int l, int r) { return Wl + (size_t)(l * 7 + r) * DIM * DIM; };
    auto BLp = [&](int l, int r) { return bl + (size_t)(l * 7 + r) * DIM; };
    auto WRp = [&](int l, int r) { return Wr + (size_t)(l * 7 + r) * DIM * DIM; };

    // --- weight prep ---
    k_addmats<<<256, 256>>>(WRp(0, 0), WRp(0, 1), WRp(0, 6), wrp1);
    k_addmats<<<256, 256>>>(WRp(0, 2), WRp(0, 4), nullptr, wra1);
    k_addmats<<<256, 256>>>(WRp(1, 0), WRp(1, 1), WRp(1, 6), wrp2);
    k_pad_wout<<<384, 256>>>(W_out, woutp);

    // --- degree counts (layer-invariant) ---
    cudaMemsetAsync(invb, 0, 6 * (size_t)NP * sizeof(float));
    k_count<<<cdiv(E_CITES, 256), 256>>>(cites_dst, invb + 0 * NP, E_CITES);
    k_count<<<cdiv(E_WRITES, 256), 256>>>(writes_dst, invb + 1 * NP, E_WRITES);
    k_count<<<cdiv(E_TOPIC, 256), 256>>>(rev_topic_dst, invb + 2 * NP, E_TOPIC);
    k_count<<<cdiv(E_WRITES, 256), 256>>>(rev_writes_dst, invb + 3 * NP, E_WRITES);
    k_count<<<cdiv(E_AFF, 256), 256>>>(rev_aff_dst, invb + 4 * NP, E_AFF);
    k_count<<<cdiv(E_TOPIC, 256), 256>>>(topic_dst, invb + 5 * NP, E_TOPIC);
    k_inv<<<cdiv(NP, 256), 256>>>(invb + 0 * NP, NP);
    k_inv<<<cdiv(NP, 256), 256>>>(invb + 1 * NP, NP);
    k_inv<<<cdiv(NP, 256), 256>>>(invb + 2 * NP, NP);
    k_inv<<<cdiv(NA, 256), 256>>>(invb + 3 * NP, NA);
    k_inv<<<cdiv(NA, 256), 256>>>(invb + 4 * NP, NA);
    k_inv<<<cdiv(NF, 256), 256>>>(invb + 5 * NP, NF);

    Seg z = {nullptr, nullptr, nullptr, nullptr};

    // ================= Layer 1: new_p =================
    cudaMemsetAsync(agg, 0, 3 * SZP * sizeof(float));
    k_scatter<<<cdiv(E_CITES * 32, 256), 256>>>(x_p, cites_src, cites_dst, agg, E_CITES);
    k_scatter<<<cdiv(E_WRITES * 32, 256), 256>>>(x_a, writes_src, writes_dst, agg + SZP, E_WRITES);
    k_scatter<<<cdiv(E_TOPIC * 32, 256), 256>>>(x_f, rev_topic_src, rev_topic_dst, agg + 2 * SZP, E_TOPIC);
    {
        Seg s0 = {agg, invb + 0 * NP, WLp(0, 0), BLp(0, 0)};
        Seg s1 = {agg + SZP, invb + 1 * NP, WLp(0, 1), BLp(0, 1)};
        Seg s2 = {agg + 2 * SZP, invb + 2 * NP, WLp(0, 6), BLp(0, 6)};
        Seg s3 = {x_p, nullptr, wrp1, nullptr};
        k_gemm<true, false><<<dim3(2, cdiv(NP, 128)), 256>>>(s0, s1, s2, s3, 4, NP, 256, 256, p1);
    }

    // ================= Layer 1: new_a =================
    cudaMemsetAsync(agg, 0, (size_t)NA * DIM * sizeof(float));
    cudaMemsetAsync(agg + SZP, 0, (size_t)NA * DIM * sizeof(float));
    k_scatter<<<cdiv(E_WRITES * 32, 256), 256>>>(x_p, rev_writes_src, rev_writes_dst, agg, E_WRITES);
    k_scatter<<<cdiv(E_AFF * 32, 256), 256>>>(x_i, rev_aff_src, rev_aff_dst, agg + SZP, E_AFF);
    {
        Seg s0 = {agg, invb + 3 * NP, WLp(0, 2), BLp(0, 2)};
        Seg s1 = {agg + SZP, invb + 4 * NP, WLp(0, 4), BLp(0, 4)};
        Seg s2 = {x_a, nullptr, wra1, nullptr};
        k_gemm<true, false><<<dim3(2, cdiv(NA, 128)), 256>>>(s0, s1, s2, z, 3, NA, 256, 256, a1);
    }

    // ================= Layer 1: new_f =================
    cudaMemsetAsync(agg, 0, (size_t)NF * DIM * sizeof(float));
    k_scatter<<<cdiv(E_TOPIC * 32, 256), 256>>>(x_p, topic_src, topic_dst, agg, E_TOPIC);
    {
        Seg s0 = {agg, invb + 5 * NP, WLp(0, 5), BLp(0, 5)};
        Seg s1 = {x_f, nullptr, WRp(0, 5), nullptr};
        k_gemm<true, false><<<dim3(2, cdiv(NF, 128)), 256>>>(s0, s1, z, z, 2, NF, 256, 256, f1);
    }

    // ================= Layer 2: new_p (only p is needed downstream) =================
    cudaMemsetAsync(agg, 0, 3 * SZP * sizeof(float));
    k_scatter<<<cdiv(E_CITES * 32, 256), 256>>>(p1, cites_src, cites_dst, agg, E_CITES);
    k_scatter<<<cdiv(E_WRITES * 32, 256), 256>>>(a1, writes_src, writes_dst, agg + SZP, E_WRITES);
    k_scatter<<<cdiv(E_TOPIC * 32, 256), 256>>>(f1, rev_topic_src, rev_topic_dst, agg + 2 * SZP, E_TOPIC);
    {
        Seg s0 = {agg, invb + 0 * NP, WLp(1, 0), BLp(1, 0)};
        Seg s1 = {agg + SZP, invb + 1 * NP, WLp(1, 1), BLp(1, 1)};
        Seg s2 = {agg + 2 * SZP, invb + 2 * NP, WLp(1, 6), BLp(1, 6)};
        Seg s3 = {p1, nullptr, wrp2, nullptr};
        k_gemm<true, false><<<dim3(2, cdiv(NP, 128)), 256>>>(s0, s1, s2, s3, 4, NP, 256, 256, p2);
    }

    // ================= Output projection =================
    {
        Seg s0 = {p2, nullptr, woutp, b_out};
        k_gemm<false, true><<<dim3(3, cdiv(NP, 128)), 256>>>(s0, z, z, z, 1, NP, 384, OUTD,
                                                             (float*)d_out);
    }
}

// round 2
// speedup vs baseline: 1.4789x; 1.4789x over previous
#include <cuda_runtime.h>
#include <mma.h>
#include <cstddef>

using namespace nvcuda;

#define NP 200000
#define NA 100000
#define NI 8000
#define NF 30000
#define DIM 256
#define OUTD 349
#define NPAD 384
#define E_CITES 500000
#define E_WRITES 400000
#define E_AFF 100000
#define E_TOPIC 300000

#define SZP ((size_t)NP * DIM)

// ---------------- scratch (device globals: no allocation allowed) ----------------
// All GEMM output buffers padded by +128 rows (store_matrix_sync writes full tiles).
__device__ float g_agg[3 * NP * DIM];
__device__ float g_p1[(NP + 128) * DIM];
__device__ float g_a1[(NA + 128) * DIM];
__device__ float g_f1[(NF + 128) * DIM];
__device__ float g_p2[(NP + 128) * DIM];
__device__ float g_opad[(size_t)(NP + 128) * NPAD];
__device__ float g_inv[6 * NP];
__device__ float g_wrp1[DIM * DIM];
__device__ float g_wra1[DIM * DIM];
__device__ float g_wrp2[DIM * DIM];
__device__ float g_woutp[DIM * NPAD];

// ---------------- small kernels ----------------
__global__ void k_count(const int* __restrict__ dst, float* cnt, int E) {
    int i = blockIdx.x * blockDim.x + threadIdx.x;
    if (i < E) atomicAdd(&cnt[dst[i]], 1.0f);
}

__global__ void k_inv(float* cnt, int n) {
    int i = blockIdx.x * blockDim.x + threadIdx.x;
    if (i < n) cnt[i] = 1.0f / fmaxf(cnt[i], 1.0f);
}

__global__ void k_addmats(const float* __restrict__ a, const float* __restrict__ b,
                          const float* __restrict__ c, float* __restrict__ out) {
    int i = blockIdx.x * blockDim.x + threadIdx.x;  // 65536 total
    float v = a[i] + b[i];
    if (c) v += c[i];
    out[i] = v;
}

__global__ void k_pad_wout(const float* __restrict__ W, float* __restrict__ Wp) {
    int i = blockIdx.x * blockDim.x + threadIdx.x;  // 256*384 total
    int r = i / NPAD, c = i % NPAD;
    Wp[i] = (c < OUTD) ? W[r * OUTD + c] : 0.0f;
}

// Compact NPx384 scratch -> NPx349 output. One block per row.
__global__ void k_compact(const float* __restrict__ src, float* __restrict__ dst) {
    int r = blockIdx.x;
    int c = threadIdx.x;
    if (c < OUTD) dst[(size_t)r * OUTD + c] = src[(size_t)r * NPAD + c];
}

// One warp per edge; mean-division fused (v *= inv[dst]); 128-bit L2 reduction.
__global__ void k_scatter(const float* __restrict__ X, const int* __restrict__ src,
                          const int* __restrict__ dst, const float* __restrict__ inv,
                          float* __restrict__ agg, int E) {
    int gt = blockIdx.x * blockDim.x + threadIdx.x;
    int e = gt >> 5;
    int lane = gt & 31;
    if (e >= E) return;
    int s = __ldg(&src[e]);
    int d = __ldg(&dst[e]);
    float iv = __ldg(&inv[d]);
    const float4* xs = reinterpret_cast<const float4*>(X + (size_t)s * DIM);
    float* ag = agg + (size_t)d * DIM;
#pragma unroll
    for (int j = 0; j < 2; j++) {
        int f4 = lane + j * 32;
        float4 v = __ldg(&xs[f4]);
        v.x *= iv; v.y *= iv; v.z *= iv; v.w *= iv;
        asm volatile("red.global.add.v4.f32 [%0], {%1,%2,%3,%4};"
                     :: "l"(ag + f4 * 4), "f"(v.x), "f"(v.y), "f"(v.z), "f"(v.w)
                     : "memory");
    }
}

// ---------------- TF32 tensor-core multi-segment GEMM ----------------
// C[M, Nld] = act( sum_s A_s @ W_s + bias )  ; A_s: [M,256], W_s: [256,Nld]
struct Seg {
    const float* A;
    const float* W;
    const float* bias;
};

__device__ __forceinline__ void cp_async16(float* smem_dst, const float* gmem_src, bool pred) {
    unsigned s = (unsigned)__cvta_generic_to_shared(smem_dst);
    int bytes = pred ? 16 : 0;
    asm volatile("cp.async.cg.shared.global [%0], [%1], 16, %2;\n"
                 :: "r"(s), "l"(gmem_src), "r"(bytes));
}

#define A_LD 36
#define B_LD 136
#define AS_FLOATS (128 * A_LD)
#define BS_FLOATS (32 * B_LD)
#define SMEM_FLOATS (2 * AS_FLOATS + 2 * BS_FLOATS + 16 * B_LD)

template <bool RELU>
__global__ __launch_bounds__(256)
void k_gemm_tc(Seg s0, Seg s1, Seg s2, Seg s3, int nseg,
               int M, int Nld, int Nbias, float* __restrict__ C) {
    extern __shared__ float sm[];
    float* As = sm;                       // [2][128 x A_LD]
    float* Bs = sm + 2 * AS_FLOATS;       // [2][32 x B_LD]
    float* brep = Bs + 2 * BS_FLOATS;     // [16 x B_LD] replicated bias rows

    const Seg segs[4] = {s0, s1, s2, s3};
    const int tid = threadIdx.x;
    const int m0 = blockIdx.y * 128;
    const int n0 = blockIdx.x * 128;

    // build replicated bias tile
    if (tid < 128) {
        int n = n0 + tid;
        float b = 0.0f;
        if (n < Nbias) {
            for (int s = 0; s < nseg; s++)
                if (segs[s].bias) b += __ldg(&segs[s].bias[n]);
        }
        for (int r = 0; r < 16; r++) brep[r * B_LD + tid] = b;
    }
    __syncthreads();

    const int warp = tid >> 5, lane = tid & 31;
    (void)lane;
    const int wm = warp & 3;   // m offset = 32*wm
    const int wn = warp >> 2;  // n offset = 64*wn

    wmma::fragment<wmma::accumulator, 16, 16, 8, float> c[2][4];
#pragma unroll
    for (int i = 0; i < 2; i++)
#pragma unroll
        for (int j = 0; j < 4; j++)
            wmma::load_matrix_sync(c[i][j], brep + wn * 64 + j * 16, B_LD, wmma::mem_row_major);

    // tile loader
    const int arow = tid >> 3;          // 0..31
    const int ac4 = (tid & 7) * 4;      // col within 32
    const int brow = tid >> 5;          // 0..7
    const int bc4 = (tid & 31) * 4;     // col within 128

    auto load_tile = [&](int t, int buf) {
        int s = t >> 3;
        int kt = (t & 7) * 32;
        const float* A = segs[s].A;
        const float* W = segs[s].W;
        float* asb = As + buf * AS_FLOATS;
#pragma unroll
        for (int h = 0; h < 4; h++) {
            int mr = arow + h * 32;
            int gm = m0 + mr;
            bool p = gm < M;
            int gms = p ? gm : (M - 1);
            cp_async16(asb + mr * A_LD + ac4, A + (size_t)gms * 256 + kt + ac4, p);
        }
        float* bsb = Bs + buf * BS_FLOATS;
#pragma unroll
        for (int h = 0; h < 4; h++) {
            int kr = brow + h * 8;
            cp_async16(bsb + kr * B_LD + bc4, W + (size_t)(kt + kr) * Nld + n0 + bc4, true);
        }
        asm volatile("cp.async.commit_group;\n" ::: "memory");
    };

    const int T = nseg * 8;
    load_tile(0, 0);
    int buf = 0;
    for (int t = 0; t < T; t++) {
        asm volatile("cp.async.wait_group 0;\n" ::: "memory");
        __syncthreads();
        if (t + 1 < T) load_tile(t + 1, buf ^ 1);

        float* asb = As + buf * AS_FLOATS;
        float* bsb = Bs + buf * BS_FLOATS;
#pragma unroll
        for (int k8 = 0; k8 < 4; k8++) {
            wmma::fragment<wmma::matrix_a, 16, 16, 8, wmma::precision::tf32, wmma::row_major> a[2];
            wmma::fragment<wmma::matrix_b, 16, 16, 8, wmma::precision::tf32, wmma::row_major> b[4];
#pragma unroll
            for (int i = 0; i < 2; i++) {
                wmma::load_matrix_sync(a[i], asb + (wm * 32 + i * 16) * A_LD + k8 * 8, A_LD);
#pragma unroll
                for (int e = 0; e < a[i].num_elements; e++)
                    a[i].x[e] = wmma::__float_to_tf32(a[i].x[e]);
            }
#pragma unroll
            for (int j = 0; j < 4; j++) {
                wmma::load_matrix_sync(b[j], bsb + (k8 * 8) * B_LD + wn * 64 + j * 16, B_LD);
#pragma unroll
                for (int e = 0; e < b[j].num_elements; e++)
                    b[j].x[e] = wmma::__float_to_tf32(b[j].x[e]);
            }
#pragma unroll
            for (int i = 0; i < 2; i++)
#pragma unroll
                for (int j = 0; j < 4; j++)
                    wmma::mma_sync(c[i][j], a[i], b[j], c[i][j]);
        }
        __syncthreads();
        buf ^= 1;
    }

    // epilogue: relu + store (buffers are row-padded, so full-tile stores are safe)
#pragma unroll
    for (int i = 0; i < 2; i++)
#pragma unroll
        for (int j = 0; j < 4; j++) {
            if (RELU) {
#pragma unroll
                for (int e = 0; e < c[i][j].num_elements; e++)
                    c[i][j].x[e] = fmaxf(c[i][j].x[e], 0.0f);
            }
            wmma::store_matrix_sync(
                C + (size_t)(m0 + wm * 32 + i * 16) * Nld + n0 + wn * 64 + j * 16,
                c[i][j], Nld, wmma::mem_row_major);
        }
}

// ---------------- orchestration ----------------
static inline int cdiv(int a, int b) { return (a + b - 1) / b; }

extern "C" void kernel_launch(void* const* d_in, const int* in_sizes, int n_in,
                              void* d_out, int out_size) {
    const float* x_p = (const float*)d_in[0];
    const float* x_a = (const float*)d_in[1];
    const float* x_i = (const float*)d_in[2];
    const float* x_f = (const float*)d_in[3];
    const int* cites_src = (const int*)d_in[4];
    const int* cites_dst = (const int*)d_in[5];
    const int* writes_src = (const int*)d_in[6];
    const int* writes_dst = (const int*)d_in[7];
    const int* rev_writes_src = (const int*)d_in[8];
    const int* rev_writes_dst = (const int*)d_in[9];
    // d_in[10..11]: aff (dead: layer-1 new_i unused downstream)
    const int* rev_aff_src = (const int*)d_in[12];
    const int* rev_aff_dst = (const int*)d_in[13];
    const int* topic_src = (const int*)d_in[14];
    const int* topic_dst = (const int*)d_in[15];
    const int* rev_topic_src = (const int*)d_in[16];
    const int* rev_topic_dst = (const int*)d_in[17];
    const float* Wl = (const float*)d_in[18];
    const float* bl = (const float*)d_in[19];
    const float* Wr = (const float*)d_in[20];
    const float* W_out = (const float*)d_in[21];
    const float* b_out = (const float*)d_in[22];

    float *agg, *p1, *a1, *f1, *p2, *opad, *invb, *wrp1, *wra1, *wrp2, *woutp;
    cudaGetSymbolAddress((void**)&agg, g_agg);
    cudaGetSymbolAddress((void**)&p1, g_p1);
    cudaGetSymbolAddress((void**)&a1, g_a1);
    cudaGetSymbolAddress((void**)&f1, g_f1);
    cudaGetSymbolAddress((void**)&p2, g_p2);
    cudaGetSymbolAddress((void**)&opad, g_opad);
    cudaGetSymbolAddress((void**)&invb, g_inv);
    cudaGetSymbolAddress((void**)&wrp1, g_wrp1);
    cudaGetSymbolAddress((void**)&wra1, g_wra1);
    cudaGetSymbolAddress((void**)&wrp2, g_wrp2);
    cudaGetSymbolAddress((void**)&woutp, g_woutp);

    const size_t SMEM_BYTES = SMEM_FLOATS * sizeof(float);
    cudaFuncSetAttribute(k_gemm_tc<true>, cudaFuncAttributeMaxDynamicSharedMemorySize,
                         (int)SMEM_BYTES);
    cudaFuncSetAttribute(k_gemm_tc<false>, cudaFuncAttributeMaxDynamicSharedMemorySize,
                         (int)SMEM_BYTES);

    auto WLp = [&](int l, int r) { return Wl + (size_t)(l * 7 + r) * DIM * DIM; };
    auto BLp = [&](int l, int r) { return bl + (size_t)(l * 7 + r) * DIM; };
    auto WRp = [&](int l, int r) { return Wr + (size_t)(l * 7 + r) * DIM * DIM; };

    // --- weight prep ---
    k_addmats<<<256, 256>>>(WRp(0, 0), WRp(0, 1), WRp(0, 6), wrp1);
    k_addmats<<<256, 256>>>(WRp(0, 2), WRp(0, 4), nullptr, wra1);
    k_addmats<<<256, 256>>>(WRp(1, 0), WRp(1, 1), WRp(1, 6), wrp2);
    k_pad_wout<<<384, 256>>>(W_out, woutp);

    // --- degree counts -> inverse (layer-invariant; needed BEFORE scatters) ---
    cudaMemsetAsync(invb, 0, 6 * (size_t)NP * sizeof(float));
    k_count<<<cdiv(E_CITES, 256), 256>>>(cites_dst, invb + 0 * NP, E_CITES);
    k_count<<<cdiv(E_WRITES, 256), 256>>>(writes_dst, invb + 1 * NP, E_WRITES);
    k_count<<<cdiv(E_TOPIC, 256), 256>>>(rev_topic_dst, invb + 2 * NP, E_TOPIC);
    k_count<<<cdiv(E_WRITES, 256), 256>>>(rev_writes_dst, invb + 3 * NP, E_WRITES);
    k_count<<<cdiv(E_AFF, 256), 256>>>(rev_aff_dst, invb + 4 * NP, E_AFF);
    k_count<<<cdiv(E_TOPIC, 256), 256>>>(topic_dst, invb + 5 * NP, E_TOPIC);
    k_inv<<<cdiv(NP, 256), 256>>>(invb + 0 * NP, NP);
    k_inv<<<cdiv(NP, 256), 256>>>(invb + 1 * NP, NP);
    k_inv<<<cdiv(NP, 256), 256>>>(invb + 2 * NP, NP);
    k_inv<<<cdiv(NA, 256), 256>>>(invb + 3 * NP, NA);
    k_inv<<<cdiv(NA, 256), 256>>>(invb + 4 * NP, NA);
    k_inv<<<cdiv(NF, 256), 256>>>(invb + 5 * NP, NF);

    Seg z = {nullptr, nullptr, nullptr};

    // ================= Layer 1: new_p =================
    cudaMemsetAsync(agg, 0, 3 * SZP * sizeof(float));
    k_scatter<<<cdiv(E_CITES * 32, 256), 256>>>(x_p, cites_src, cites_dst, invb + 0 * NP, agg, E_CITES);
    k_scatter<<<cdiv(E_WRITES * 32, 256), 256>>>(x_a, writes_src, writes_dst, invb + 1 * NP, agg + SZP, E_WRITES);
    k_scatter<<<cdiv(E_TOPIC * 32, 256), 256>>>(x_f, rev_topic_src, rev_topic_dst, invb + 2 * NP, agg + 2 * SZP, E_TOPIC);
    {
        Seg s0 = {agg, WLp(0, 0), BLp(0, 0)};
        Seg s1 = {agg + SZP, WLp(0, 1), BLp(0, 1)};
        Seg s2 = {agg + 2 * SZP, WLp(0, 6), BLp(0, 6)};
        Seg s3 = {x_p, wrp1, nullptr};
        k_gemm_tc<true><<<dim3(2, cdiv(NP, 128)), 256, SMEM_BYTES>>>(
            s0, s1, s2, s3, 4, NP, 256, 256, p1);
    }

    // ================= Layer 1: new_a =================
    cudaMemsetAsync(agg, 0, (size_t)NA * DIM * sizeof(float));
    cudaMemsetAsync(agg + SZP, 0, (size_t)NA * DIM * sizeof(float));
    k_scatter<<<cdiv(E_WRITES * 32, 256), 256>>>(x_p, rev_writes_src, rev_writes_dst, invb + 3 * NP, agg, E_WRITES);
    k_scatter<<<cdiv(E_AFF * 32, 256), 256>>>(x_i, rev_aff_src, rev_aff_dst, invb + 4 * NP, agg + SZP, E_AFF);
    {
        Seg s0 = {agg, WLp(0, 2), BLp(0, 2)};
        Seg s1 = {agg + SZP, WLp(0, 4), BLp(0, 4)};
        Seg s2 = {x_a, wra1, nullptr};
        k_gemm_tc<true><<<dim3(2, cdiv(NA, 128)), 256, SMEM_BYTES>>>(
            s0, s1, s2, z, 3, NA, 256, 256, a1);
    }

    // ================= Layer 1: new_f =================
    cudaMemsetAsync(agg, 0, (size_t)NF * DIM * sizeof(float));
    k_scatter<<<cdiv(E_TOPIC * 32, 256), 256>>>(x_p, topic_src, topic_dst, invb + 5 * NP, agg, E_TOPIC);
    {
        Seg s0 = {agg, WLp(0, 5), BLp(0, 5)};
        Seg s1 = {x_f, WRp(0, 5), nullptr};
        k_gemm_tc<true><<<dim3(2, cdiv(NF, 128)), 256, SMEM_BYTES>>>(
            s0, s1, z, z, 2, NF, 256, 256, f1);
    }

    // ================= Layer 2: new_p (only p needed downstream) =================
    cudaMemsetAsync(agg, 0, 3 * SZP * sizeof(float));
    k_scatter<<<cdiv(E_CITES * 32, 256), 256>>>(p1, cites_src, cites_dst, invb + 0 * NP, agg, E_CITES);
    k_scatter<<<cdiv(E_WRITES * 32, 256), 256>>>(a1, writes_src, writes_dst, invb + 1 * NP, agg + SZP, E_WRITES);
    k_scatter<<<cdiv(E_TOPIC * 32, 256), 256>>>(f1, rev_topic_src, rev_topic_dst, invb + 2 * NP, agg + 2 * SZP, E_TOPIC);
    {
        Seg s0 = {agg, WLp(1, 0), BLp(1, 0)};
        Seg s1 = {agg + SZP, WLp(1, 1), BLp(1, 1)};
        Seg s2 = {agg + 2 * SZP, WLp(1, 6), BLp(1, 6)};
        Seg s3 = {p1, wrp2, nullptr};
        k_gemm_tc<true><<<dim3(2, cdiv(NP, 128)), 256, SMEM_BYTES>>>(
            s0, s1, s2, s3, 4, NP, 256, 256, p2);
    }

    // ================= Output projection (into padded scratch) =================
    {
        Seg s0 = {p2, woutp, b_out};
        k_gemm_tc<false><<<dim3(3, cdiv(NP, 128)), 256, SMEM_BYTES>>>(
            s0, z, z, z, 1, NP, NPAD, OUTD, opad);
    }
    // compact 384 -> 349 into d_out
    k_compact<<<NP, 384>>>(opad, (float*)d_out);
}